// round 3
// baseline (speedup 1.0000x reference)
#include <cuda_runtime.h>
#include <cstdint>

// Spike-latency encoder:
//   trace:  [B=1024, F=128] f32
//   center: [C=8] f32
//   out:    [T=100, B=1024, N=F*C=1024] one-hot along T per (b,n),
//           written as float32 (bench canonicalizes int outputs to f32).
//
// out[t,b,f*8+c] = (bin(b,f,c) == t) ? 1.0f : 0.0f
//   bin = trunc( sel(2.5*|trace[b,f]-center[c]|) / 0.1 + 1 )
//   sel(x) = (x > 10.0f) ? 10.1f : x     (bin then 102 -> never matches)
//
// Pure HBM write-bandwidth bound: 419 MB of stores.

#define BB 1024
#define FF 128
#define CC 8
#define NN 1024
#define TT 100

__global__ void __launch_bounds__(256, 4)
spike_latency_kernel(const float* __restrict__ trace,
                     const float* __restrict__ center,
                     float* __restrict__ out) {
    const int b   = blockIdx.x;        // 0..1023
    const int tid = threadIdx.x;       // 0..255
    const int n0  = tid << 2;          // 4 consecutive n per thread
    const int f   = n0 >> 3;           // all 4 n share one feature
    const int c0  = n0 & 7;            // 0 or 4

    const float tv = __ldg(&trace[b * FF + f]);

    int bins[4];
#pragma unroll
    for (int j = 0; j < 4; j++) {
        float ct = __ldg(&center[c0 + j]);
        float tm = 2.5f * fabsf(tv - ct);          // SCALING * |diff|  (f32)
        if (tm > 10.0f) tm = 10.1f;                // cutoff -> TIME_LENGTH + DT
        // bins = trunc(times/DT + 1), IEEE f32 divide (match XLA div.rn)
        bins[j] = (int)(__fdiv_rn(tm, 0.1f) + 1.0f);
    }

    // Base float4 pointer for (t=0, b, n0); stride between t-slabs in float4.
    float4* outp = reinterpret_cast<float4*>(out + (size_t)b * NN + n0);
    const size_t stride4 = (size_t)BB * NN / 4;    // 262144 float4 per t-slab

#pragma unroll 4
    for (int t = 0; t < TT; t++) {
        float4 v;
        v.x = (bins[0] == t) ? 1.0f : 0.0f;
        v.y = (bins[1] == t) ? 1.0f : 0.0f;
        v.z = (bins[2] == t) ? 1.0f : 0.0f;
        v.w = (bins[3] == t) ? 1.0f : 0.0f;
        // streaming store: the 419MB stream cannot profit from L2 residency
        __stcs(outp + (size_t)t * stride4, v);
    }
}

extern "C" void kernel_launch(void* const* d_in, const int* in_sizes, int n_in,
                              void* d_out, int out_size) {
    // Identify inputs by element count — robust to metadata ordering:
    //   trace  : 1024*128 = 131072 floats
    //   center : 8 floats
    //   dummies: 1 element each
    const float* trace  = nullptr;
    const float* center = nullptr;
    for (int i = 0; i < n_in; i++) {
        if (in_sizes[i] == BB * FF)     trace  = (const float*)d_in[i];
        else if (in_sizes[i] == CC)     center = (const float*)d_in[i];
    }
    // Fallback to positional if sizes were unexpected
    if (!trace)  trace  = (const float*)d_in[0];
    if (!center) center = (const float*)d_in[1];

    float* out = (float*)d_out;  // [100, 1024, 1024], f32 one-hot

    spike_latency_kernel<<<BB, 256>>>(trace, center, out);
}

// round 4
// speedup vs baseline: 1.1090x; 1.1090x over previous
#include <cuda_runtime.h>
#include <cstdint>

// Spike-latency encoder:
//   trace:  [B=1024, F=128] f32
//   center: [C=8] f32
//   out:    [T=100, B=1024, N=F*C=1024] f32 one-hot along T per (b,n)
//
// out[t,b,f*8+c] = (bin(b,f,c) == t) ? 1.0f : 0.0f
//   bin = trunc( sel(2.5*|trace[b,f]-center[c]|) / 0.1 + 1 )
//   sel(x) = (x > 10.0f) ? 10.1f : x     (bin -> 102, never matches)
//
// 419 MB pure write stream. R3 showed DRAM only 66.8% busy with nothing
// else saturated -> under-fed. This round: 4x block concurrency (t split
// into 4 chunks of 25) + fully unrolled store batch per warp.

#define BB 1024
#define FF 128
#define CC 8
#define NN 1024
#define TT 100
#define TCH 25          // t-slabs per block (TT / 4)

__global__ void __launch_bounds__(256)
spike_latency_kernel(const float* __restrict__ trace,
                     const float* __restrict__ center,
                     float* __restrict__ out) {
    const int b   = blockIdx.x & (BB - 1);   // 0..1023 (fast-varying)
    const int tc  = blockIdx.x >> 10;        // 0..3    t-chunk
    const int tid = threadIdx.x;             // 0..255
    const int n0  = tid << 2;                // 4 consecutive n per thread
    const int f   = n0 >> 3;                 // all 4 n share one feature
    const int c0  = n0 & 7;                  // 0 or 4

    const float tv = __ldg(&trace[b * FF + f]);

    int bins[4];
#pragma unroll
    for (int j = 0; j < 4; j++) {
        float ct = __ldg(&center[c0 + j]);
        float tm = 2.5f * fabsf(tv - ct);          // SCALING * |diff|  (f32)
        if (tm > 10.0f) tm = 10.1f;                // cutoff -> TIME_LENGTH + DT
        // bins = trunc(times/DT + 1), IEEE f32 divide (match XLA div.rn)
        bins[j] = (int)(__fdiv_rn(tm, 0.1f) + 1.0f);
    }

    // Base float4 pointer for (t = tc*TCH, b, n0)
    const size_t stride4 = (size_t)BB * NN / 4;    // 262144 float4 per t-slab
    float4* outp = reinterpret_cast<float4*>(out + (size_t)b * NN + n0)
                 + (size_t)(tc * TCH) * stride4;

#pragma unroll
    for (int i = 0; i < TCH; i++) {
        const int t = tc * TCH + i;
        float4 v;
        v.x = (bins[0] == t) ? 1.0f : 0.0f;
        v.y = (bins[1] == t) ? 1.0f : 0.0f;
        v.z = (bins[2] == t) ? 1.0f : 0.0f;
        v.w = (bins[3] == t) ? 1.0f : 0.0f;
        // streaming store: 419MB stream cannot profit from L2 residency
        __stcs(outp + (size_t)i * stride4, v);
    }
}

extern "C" void kernel_launch(void* const* d_in, const int* in_sizes, int n_in,
                              void* d_out, int out_size) {
    // Identify inputs by element count — robust to metadata ordering:
    //   trace  : 1024*128 = 131072 floats,  center : 8 floats, dummies: 1 each
    const float* trace  = nullptr;
    const float* center = nullptr;
    for (int i = 0; i < n_in; i++) {
        if (in_sizes[i] == BB * FF)     trace  = (const float*)d_in[i];
        else if (in_sizes[i] == CC)     center = (const float*)d_in[i];
    }
    if (!trace)  trace  = (const float*)d_in[0];
    if (!center) center = (const float*)d_in[1];

    float* out = (float*)d_out;  // [100, 1024, 1024] f32 one-hot

    spike_latency_kernel<<<BB * 4, 256>>>(trace, center, out);
}

// round 5
// speedup vs baseline: 1.1360x; 1.0243x over previous
#include <cuda_runtime.h>
#include <cstdint>

// Spike-latency encoder:
//   trace:  [B=1024, F=128] f32
//   center: [C=8] f32
//   out:    [T=100, B=1024, N=F*C=1024] f32 one-hot along T per (b,n)
//
// out[t,b,f*8+c] = (bin(b,f,c) == t) ? 1.0f : 0.0f
//   bin = trunc( sel(2.5*|trace[b,f]-center[c]|) / 0.1 + 1 )
//   sel(x) = (x > 10.0f) ? 10.1f : x     (bin -> 102, never matches)
//
// 419 MB pure write stream. R4: DRAM 75.2%, occ 64.7% (regs=34 -> 7 CTA/SM).
// R5: cap regs at 32 (launch_bounds(256,8)) + 10-way t-split for smoother
// waves and a permanently full store queue.

#define BB 1024
#define FF 128
#define CC 8
#define NN 1024
#define TT 100
#define NCH 10          // number of t-chunks
#define TCH 10          // t-slabs per block (TT / NCH)

__global__ void __launch_bounds__(256, 8)
spike_latency_kernel(const float* __restrict__ trace,
                     const float* __restrict__ center,
                     float* __restrict__ out) {
    const int b   = blockIdx.x & (BB - 1);   // 0..1023 (fast-varying)
    const int tc  = blockIdx.x >> 10;        // 0..9    t-chunk
    const int tid = threadIdx.x;             // 0..255
    const int n0  = tid << 2;                // 4 consecutive n per thread
    const int f   = n0 >> 3;                 // all 4 n share one feature
    const int c0  = n0 & 7;                  // 0 or 4

    const float tv = __ldg(&trace[b * FF + f]);

    int bins[4];
#pragma unroll
    for (int j = 0; j < 4; j++) {
        float ct = __ldg(&center[c0 + j]);
        float tm = 2.5f * fabsf(tv - ct);          // SCALING * |diff|  (f32)
        if (tm > 10.0f) tm = 10.1f;                // cutoff -> TIME_LENGTH + DT
        // bins = trunc(times/DT + 1), IEEE f32 divide (match XLA div.rn)
        bins[j] = (int)(__fdiv_rn(tm, 0.1f) + 1.0f);
    }

    // Base float4 pointer for (t = tc*TCH, b, n0)
    const size_t stride4 = (size_t)BB * NN / 4;    // 262144 float4 per t-slab
    float4* outp = reinterpret_cast<float4*>(out + (size_t)b * NN + n0)
                 + (size_t)(tc * TCH) * stride4;

    const int tbase = tc * TCH;
#pragma unroll
    for (int i = 0; i < TCH; i++) {
        const int t = tbase + i;
        float4 v;
        v.x = (bins[0] == t) ? 1.0f : 0.0f;
        v.y = (bins[1] == t) ? 1.0f : 0.0f;
        v.z = (bins[2] == t) ? 1.0f : 0.0f;
        v.w = (bins[3] == t) ? 1.0f : 0.0f;
        // streaming store: 419MB stream cannot profit from L2 residency
        __stcs(outp + (size_t)i * stride4, v);
    }
}

extern "C" void kernel_launch(void* const* d_in, const int* in_sizes, int n_in,
                              void* d_out, int out_size) {
    // Identify inputs by element count — robust to metadata ordering:
    //   trace  : 1024*128 = 131072 floats,  center : 8 floats, dummies: 1 each
    const float* trace  = nullptr;
    const float* center = nullptr;
    for (int i = 0; i < n_in; i++) {
        if (in_sizes[i] == BB * FF)     trace  = (const float*)d_in[i];
        else if (in_sizes[i] == CC)     center = (const float*)d_in[i];
    }
    if (!trace)  trace  = (const float*)d_in[0];
    if (!center) center = (const float*)d_in[1];

    float* out = (float*)d_out;  // [100, 1024, 1024] f32 one-hot

    spike_latency_kernel<<<BB * NCH, 256>>>(trace, center, out);
}